// round 2
// baseline (speedup 1.0000x reference)
#include <cuda_runtime.h>
#include <math.h>

#define IN_C   64
#define OUT_C  64
#define NUM_RELS 32
#define N_NODES 20000
#define N_EDGES 50000
#define CHUNKS 4          // blocks per (dir,type) bucket in the edge kernel

// ---------------- device scratch (no allocation allowed) ----------------
__device__ int   g_cnt_src[N_NODES];
__device__ int   g_cnt_dst[N_NODES];
__device__ int   g_hist[NUM_RELS];
__device__ int   g_off[NUM_RELS + 1];
__device__ int   g_cursor[NUM_RELS];
__device__ int   g_esrc[N_EDGES];
__device__ int   g_edst[N_EDGES];
__device__ float g_Wn[2 * NUM_RELS * IN_C * OUT_C];   // 64 normalized 64x64 mats, 1MB

// ---------------- k0: zero counters ----------------
__global__ void k_zero() {
    int i = blockIdx.x * blockDim.x + threadIdx.x;
    if (i < N_NODES) { g_cnt_src[i] = 0; g_cnt_dst[i] = 0; }
    if (i < NUM_RELS) { g_hist[i] = 0; g_cursor[i] = 0; }
}

// ---------------- k1: node degree counts + type histogram ----------------
// NOTE: edge_index / edge_type are int32 on the wire (JAX x64 disabled).
__global__ void k_count(const int* __restrict__ ei,
                        const int* __restrict__ et) {
    int e = blockIdx.x * blockDim.x + threadIdx.x;
    if (e < N_EDGES) {
        int s = ei[e];
        int d = ei[N_EDGES + e];
        int t = et[e];
        atomicAdd(&g_cnt_src[s], 1);
        atomicAdd(&g_cnt_dst[d], 1);
        atomicAdd(&g_hist[t], 1);
    }
}

// ---------------- k2: exclusive scan over 32 bins ----------------
__global__ void k_scan() {
    if (threadIdx.x == 0 && blockIdx.x == 0) {
        int acc = 0;
        for (int t = 0; t < NUM_RELS; t++) { g_off[t] = acc; acc += g_hist[t]; }
        g_off[NUM_RELS] = acc;
    }
}

// ---------------- k3: bucket edges by type (counting-sort scatter) ----------------
__global__ void k_scatter(const int* __restrict__ ei,
                          const int* __restrict__ et) {
    int e = blockIdx.x * blockDim.x + threadIdx.x;
    if (e < N_EDGES) {
        int t = et[e];
        int p = g_off[t] + atomicAdd(&g_cursor[t], 1);
        g_esrc[p] = ei[e];
        g_edst[p] = ei[N_EDGES + e];
    }
}

// ---------------- k4: per-relation weight normalization ----------------
// block m in [0,64): m<32 -> weight_fwd row m ; else weight_bwd row m-32
__global__ void k_norm(const float* __restrict__ wf, const float* __restrict__ wb) {
    int m = blockIdx.x;
    const float* src = (m < NUM_RELS) ? (wf + (size_t)m * 4096)
                                      : (wb + (size_t)(m - NUM_RELS) * 4096);
    float* dst = g_Wn + (size_t)m * 4096;
    __shared__ float red[256];
    float s = 0.f;
    for (int j = threadIdx.x; j < 4096; j += 256) { float v = src[j]; s += v * v; }
    red[threadIdx.x] = s;
    __syncthreads();
    for (int w = 128; w > 0; w >>= 1) {
        if (threadIdx.x < w) red[threadIdx.x] += red[threadIdx.x + w];
        __syncthreads();
    }
    float scale = 1.0f / (sqrtf(red[0]) + 0.01f);
    for (int j = threadIdx.x; j < 4096; j += 256) dst[j] = src[j] * scale;
}

// ---------------- k5: out = x @ lin_w^T + lin_b (dense init) ----------------
__global__ void __launch_bounds__(256) k_linear(const float* __restrict__ x,
                                                const float* __restrict__ lw,
                                                const float* __restrict__ lb,
                                                float* __restrict__ out) {
    __shared__ float Ls[64 * 64];   // Ls[i*64+o] = lw[o*64+i] (transposed for bcast reads)
    __shared__ float Bs[64];
    for (int j = threadIdx.x; j < 4096; j += 256) {
        int o = j >> 6, i = j & 63;
        Ls[i * 64 + o] = lw[j];
    }
    if (threadIdx.x < 64) Bs[threadIdx.x] = lb[threadIdx.x];
    __syncthreads();

    int n = blockIdx.x * 256 + threadIdx.x;
    if (n >= N_NODES) return;

    float4 acc[16];
#pragma unroll
    for (int k = 0; k < 16; k++) acc[k] = make_float4(0.f, 0.f, 0.f, 0.f);

    const float4* xr = (const float4*)(x + (size_t)n * 64);
    const float4* L4 = (const float4*)Ls;
#pragma unroll 1
    for (int i4 = 0; i4 < 16; i4++) {
        float4 v = xr[i4];
        float vs[4] = {v.x, v.y, v.z, v.w};
#pragma unroll
        for (int j = 0; j < 4; j++) {
            float vi = vs[j];
            const float4* wrow = L4 + (i4 * 4 + j) * 16;
#pragma unroll
            for (int o = 0; o < 16; o++) {
                float4 w = wrow[o];
                acc[o].x += vi * w.x; acc[o].y += vi * w.y;
                acc[o].z += vi * w.z; acc[o].w += vi * w.w;
            }
        }
    }
    float4* outr = (float4*)(out + (size_t)n * 64);
    const float4* B4 = (const float4*)Bs;
#pragma unroll
    for (int o = 0; o < 16; o++) {
        float4 b = B4[o];
        outr[o] = make_float4(acc[o].x + b.x, acc[o].y + b.y,
                              acc[o].z + b.z, acc[o].w + b.w);
    }
}

// ---------------- k6: edge message kernel (one (dir,type,chunk) per block) ----------------
// dir=0: msg = x[src] @ Wfwd[t] / (cnt_src[src]+1), scatter-add at dst
// dir=1: msg = x[dst] @ Wbwd[t] / (cnt_dst[dst]+1), scatter-add at src
__global__ void __launch_bounds__(256) k_edge(const float* __restrict__ x,
                                              float* __restrict__ out) {
    __shared__ float Ws[4096];
    int b = blockIdx.x;
    int dir = b & 1;
    int t = (b >> 1) & 31;
    int chunk = b >> 6;

    const float4* Wg = (const float4*)(g_Wn + (size_t)(dir * NUM_RELS + t) * 4096);
    float4* Ws4w = (float4*)Ws;
    for (int j = threadIdx.x; j < 1024; j += 256) Ws4w[j] = Wg[j];
    __syncthreads();

    int start = g_off[t], end = g_off[t + 1];
    const float4* W4 = (const float4*)Ws;

    for (int idx = start + chunk * 256 + threadIdx.x; idx < end; idx += 256 * CHUNKS) {
        int row, onode;
        float scale;
        if (dir == 0) {
            row = g_esrc[idx]; onode = g_edst[idx];
            scale = 1.0f / (float)(g_cnt_src[row] + 1);
        } else {
            row = g_edst[idx]; onode = g_esrc[idx];
            scale = 1.0f / (float)(g_cnt_dst[row] + 1);
        }

        float4 acc[16];
#pragma unroll
        for (int k = 0; k < 16; k++) acc[k] = make_float4(0.f, 0.f, 0.f, 0.f);

        const float4* xr = (const float4*)(x + (size_t)row * 64);
#pragma unroll 1
        for (int i4 = 0; i4 < 16; i4++) {
            float4 v = xr[i4];
            float vs[4] = {v.x, v.y, v.z, v.w};
#pragma unroll
            for (int j = 0; j < 4; j++) {
                float vi = vs[j];
                const float4* wrow = W4 + (i4 * 4 + j) * 16;   // bcast LDS.128
#pragma unroll
                for (int o = 0; o < 16; o++) {
                    float4 w = wrow[o];
                    acc[o].x += vi * w.x; acc[o].y += vi * w.y;
                    acc[o].z += vi * w.z; acc[o].w += vi * w.w;
                }
            }
        }

        float* op = out + (size_t)onode * 64;
#pragma unroll
        for (int o = 0; o < 16; o++) {
            float ax = acc[o].x * scale, ay = acc[o].y * scale;
            float az = acc[o].z * scale, aw = acc[o].w * scale;
            asm volatile("red.global.add.v4.f32 [%0], {%1, %2, %3, %4};"
                         :: "l"(op + o * 4), "f"(ax), "f"(ay), "f"(az), "f"(aw)
                         : "memory");
        }
    }
}

// ---------------- launch ----------------
extern "C" void kernel_launch(void* const* d_in, const int* in_sizes, int n_in,
                              void* d_out, int out_size) {
    const float* x   = (const float*)d_in[0];
    const int*   ei  = (const int*)d_in[1];     // [2, E] int32 (JAX x64 disabled)
    const int*   et  = (const int*)d_in[2];     // [E]    int32
    const float* wf  = (const float*)d_in[3];   // [32, 4096]
    const float* wb  = (const float*)d_in[4];   // [32, 4096]
    const float* lw  = (const float*)d_in[5];   // [64, 64]
    const float* lb  = (const float*)d_in[6];   // [64]
    float*       out = (float*)d_out;           // [20000, 64]

    (void)in_sizes; (void)n_in; (void)out_size;

    k_zero<<<(N_NODES + 255) / 256, 256>>>();
    k_count<<<(N_EDGES + 255) / 256, 256>>>(ei, et);
    k_scan<<<1, 32>>>();
    k_scatter<<<(N_EDGES + 255) / 256, 256>>>(ei, et);
    k_norm<<<2 * NUM_RELS, 256>>>(wf, wb);
    k_linear<<<(N_NODES + 255) / 256, 256>>>(x, lw, lb, out);
    k_edge<<<2 * NUM_RELS * CHUNKS, 256>>>(x, out);
}

// round 3
// speedup vs baseline: 1.2924x; 1.2924x over previous
#include <cuda_runtime.h>
#include <math.h>

#define IN_C   64
#define OUT_C  64
#define NUM_RELS 32
#define N_NODES 20000
#define N_EDGES 50000
#define CHUNKS 4

// ---------------- device scratch ----------------
__device__ int   g_cnt_src[N_NODES];
__device__ int   g_cnt_dst[N_NODES];
__device__ int   g_hist[NUM_RELS];
__device__ int   g_off[NUM_RELS + 1];
__device__ int   g_cursor[NUM_RELS];
__device__ int   g_esrc[N_EDGES];
__device__ int   g_edst[N_EDGES];
__device__ float g_Wn[2 * NUM_RELS * IN_C * OUT_C];   // 64 normalized 64x64 mats

// ---- packed f32x2 helpers (Blackwell fp32x2 pipe; ptxas won't emit these) ----
__device__ __forceinline__ void fma2(unsigned long long& d,
                                     unsigned long long a, unsigned long long b) {
    asm("fma.rn.f32x2 %0, %1, %2, %0;" : "+l"(d) : "l"(a), "l"(b));
}
__device__ __forceinline__ unsigned long long pack2(float v) {
    unsigned long long r;
    asm("mov.b64 %0, {%1, %1};" : "=l"(r) : "f"(v));
    return r;
}
__device__ __forceinline__ void mul2(unsigned long long& d,
                                     unsigned long long a, unsigned long long b) {
    asm("mul.rn.f32x2 %0, %1, %2;" : "=l"(d) : "l"(a), "l"(b));
}
__device__ __forceinline__ void unpack2(unsigned long long v, float& lo, float& hi) {
    asm("mov.b64 {%0, %1}, %2;" : "=f"(lo), "=f"(hi) : "l"(v));
}
__device__ __forceinline__ unsigned long long d_as_ull(double d) {
    return __double_as_longlong(d);
}

// ---------------- k0: zero counters ----------------
__global__ void k_zero() {
    int i = blockIdx.x * blockDim.x + threadIdx.x;
    if (i < N_NODES) { g_cnt_src[i] = 0; g_cnt_dst[i] = 0; }
    if (i < NUM_RELS) { g_hist[i] = 0; g_cursor[i] = 0; }
}

// ---------------- k1: degree counts + aggregated type histogram ----------------
__global__ void k_count(const int* __restrict__ ei, const int* __restrict__ et) {
    __shared__ int sh[NUM_RELS];
    if (threadIdx.x < NUM_RELS) sh[threadIdx.x] = 0;
    __syncthreads();
    int e = blockIdx.x * blockDim.x + threadIdx.x;
    if (e < N_EDGES) {
        atomicAdd(&g_cnt_src[ei[e]], 1);
        atomicAdd(&g_cnt_dst[ei[N_EDGES + e]], 1);
        atomicAdd(&sh[et[e]], 1);
    }
    __syncthreads();
    if (threadIdx.x < NUM_RELS && sh[threadIdx.x])
        atomicAdd(&g_hist[threadIdx.x], sh[threadIdx.x]);
}

// ---------------- k2: warp-shfl exclusive scan over 32 bins ----------------
__global__ void k_scan() {
    int t = threadIdx.x;          // 32 threads
    int s = g_hist[t];
    #pragma unroll
    for (int d = 1; d < 32; d <<= 1) {
        int n = __shfl_up_sync(0xffffffffu, s, d);
        if (t >= d) s += n;
    }
    g_off[t + 1] = s;
    if (t == 0) g_off[0] = 0;
}

// ---------------- k3: block-aggregated counting-sort scatter ----------------
__global__ void k_scatter(const int* __restrict__ ei, const int* __restrict__ et) {
    __shared__ int lh[NUM_RELS];
    __shared__ int lbase[NUM_RELS];
    if (threadIdx.x < NUM_RELS) lh[threadIdx.x] = 0;
    __syncthreads();
    int e = blockIdx.x * blockDim.x + threadIdx.x;
    int t = -1, myrank = 0;
    if (e < N_EDGES) {
        t = et[e];
        myrank = atomicAdd(&lh[t], 1);
    }
    __syncthreads();
    if (threadIdx.x < NUM_RELS) {
        int c = lh[threadIdx.x];
        lbase[threadIdx.x] = c ? atomicAdd(&g_cursor[threadIdx.x], c) : 0;
    }
    __syncthreads();
    if (e < N_EDGES) {
        int p = g_off[t] + lbase[t] + myrank;
        g_esrc[p] = ei[e];
        g_edst[p] = ei[N_EDGES + e];
    }
}

// ---------------- k4: per-relation weight normalization ----------------
__global__ void k_norm(const float* __restrict__ wf, const float* __restrict__ wb) {
    int m = blockIdx.x;
    const float4* src = (const float4*)((m < NUM_RELS)
                        ? (wf + (size_t)m * 4096)
                        : (wb + (size_t)(m - NUM_RELS) * 4096));
    float4* dst = (float4*)(g_Wn + (size_t)m * 4096);
    __shared__ float red[256];
    float s = 0.f;
    float4 v[4];
    #pragma unroll
    for (int j = 0; j < 4; j++) {
        v[j] = src[threadIdx.x + j * 256];
        s += v[j].x * v[j].x + v[j].y * v[j].y + v[j].z * v[j].z + v[j].w * v[j].w;
    }
    // warp reduce then block reduce
    #pragma unroll
    for (int d = 16; d > 0; d >>= 1) s += __shfl_xor_sync(0xffffffffu, s, d);
    if ((threadIdx.x & 31) == 0) red[threadIdx.x >> 5] = s;
    __syncthreads();
    if (threadIdx.x == 0) {
        float tot = 0.f;
        #pragma unroll
        for (int w = 0; w < 8; w++) tot += red[w];
        red[0] = 1.0f / (sqrtf(tot) + 0.01f);
    }
    __syncthreads();
    float scale = red[0];
    #pragma unroll
    for (int j = 0; j < 4; j++) {
        dst[threadIdx.x + j * 256] = make_float4(v[j].x * scale, v[j].y * scale,
                                                 v[j].z * scale, v[j].w * scale);
    }
}

// ---------------- k5: out = x @ lin_w^T + lin_b (f32x2) ----------------
__global__ void __launch_bounds__(256) k_linear(const float* __restrict__ x,
                                                const float* __restrict__ lw,
                                                const float* __restrict__ lb,
                                                float* __restrict__ out) {
    __shared__ __align__(16) float Ls[64 * 64];   // Ls[i*64+o] = lw[o*64+i]
    __shared__ float Bs[64];
    for (int j = threadIdx.x; j < 4096; j += 256) {
        int o = j >> 6, i = j & 63;
        Ls[i * 64 + o] = lw[j];
    }
    if (threadIdx.x < 64) Bs[threadIdx.x] = lb[threadIdx.x];
    __syncthreads();

    int n = blockIdx.x * 256 + threadIdx.x;
    if (n >= N_NODES) return;

    unsigned long long acc[32];
    #pragma unroll
    for (int k = 0; k < 32; k++) acc[k] = 0ull;

    const float4* xr = (const float4*)(x + (size_t)n * 64);
    #pragma unroll 1
    for (int i4 = 0; i4 < 16; i4++) {
        float4 v = xr[i4];
        float vs[4] = {v.x, v.y, v.z, v.w};
        #pragma unroll
        for (int j = 0; j < 4; j++) {
            unsigned long long vv = pack2(vs[j]);
            const double2* wrow = (const double2*)(Ls + ((i4 * 4 + j) << 6));
            #pragma unroll
            for (int o4 = 0; o4 < 16; o4++) {
                double2 w = wrow[o4];
                fma2(acc[2 * o4], vv, d_as_ull(w.x));
                fma2(acc[2 * o4 + 1], vv, d_as_ull(w.y));
            }
        }
    }
    float4* outr = (float4*)(out + (size_t)n * 64);
    const float4* B4 = (const float4*)Bs;
    #pragma unroll
    for (int o = 0; o < 16; o++) {
        float a0, a1, a2, a3;
        unpack2(acc[2 * o], a0, a1);
        unpack2(acc[2 * o + 1], a2, a3);
        float4 b = B4[o];
        outr[o] = make_float4(a0 + b.x, a1 + b.y, a2 + b.z, a3 + b.w);
    }
}

// ---------------- k6: edge message kernel (f32x2) ----------------
__global__ void __launch_bounds__(256) k_edge(const float* __restrict__ x,
                                              float* __restrict__ out) {
    __shared__ __align__(16) float Ws[4096];
    int b = blockIdx.x;
    int dir = b & 1;
    int t = (b >> 1) & 31;
    int chunk = b >> 6;

    const float4* Wg = (const float4*)(g_Wn + (size_t)(dir * NUM_RELS + t) * 4096);
    float4* Ws4w = (float4*)Ws;
    for (int j = threadIdx.x; j < 1024; j += 256) Ws4w[j] = Wg[j];
    __syncthreads();

    int start = g_off[t], end = g_off[t + 1];

    for (int idx = start + chunk * 256 + threadIdx.x; idx < end; idx += 256 * CHUNKS) {
        int row, onode;
        float scale;
        if (dir == 0) {
            row = g_esrc[idx]; onode = g_edst[idx];
            scale = 1.0f / (float)(g_cnt_src[row] + 1);
        } else {
            row = g_edst[idx]; onode = g_esrc[idx];
            scale = 1.0f / (float)(g_cnt_dst[row] + 1);
        }

        unsigned long long acc[32];
        #pragma unroll
        for (int k = 0; k < 32; k++) acc[k] = 0ull;

        const float4* xr = (const float4*)(x + (size_t)row * 64);
        #pragma unroll 1
        for (int i4 = 0; i4 < 16; i4++) {
            float4 v = xr[i4];
            float vs[4] = {v.x, v.y, v.z, v.w};
            #pragma unroll
            for (int j = 0; j < 4; j++) {
                unsigned long long vv = pack2(vs[j]);
                const double2* wrow = (const double2*)(Ws + ((i4 * 4 + j) << 6));
                #pragma unroll
                for (int o4 = 0; o4 < 16; o4++) {
                    double2 w = wrow[o4];      // LDS.128 broadcast -> two f32x2
                    fma2(acc[2 * o4], vv, d_as_ull(w.x));
                    fma2(acc[2 * o4 + 1], vv, d_as_ull(w.y));
                }
            }
        }

        unsigned long long ss = pack2(scale);
        float* op = out + (size_t)onode * 64;
        #pragma unroll
        for (int o = 0; o < 16; o++) {
            unsigned long long p0, p1;
            mul2(p0, acc[2 * o], ss);
            mul2(p1, acc[2 * o + 1], ss);
            float a0, a1, a2, a3;
            unpack2(p0, a0, a1);
            unpack2(p1, a2, a3);
            asm volatile("red.global.add.v4.f32 [%0], {%1, %2, %3, %4};"
                         :: "l"(op + o * 4), "f"(a0), "f"(a1), "f"(a2), "f"(a3)
                         : "memory");
        }
    }
}

// ---------------- launch ----------------
extern "C" void kernel_launch(void* const* d_in, const int* in_sizes, int n_in,
                              void* d_out, int out_size) {
    const float* x   = (const float*)d_in[0];
    const int*   ei  = (const int*)d_in[1];     // [2, E] int32
    const int*   et  = (const int*)d_in[2];     // [E]    int32
    const float* wf  = (const float*)d_in[3];
    const float* wb  = (const float*)d_in[4];
    const float* lw  = (const float*)d_in[5];
    const float* lb  = (const float*)d_in[6];
    float*       out = (float*)d_out;

    (void)in_sizes; (void)n_in; (void)out_size;

    k_zero<<<(N_NODES + 255) / 256, 256>>>();
    k_count<<<(N_EDGES + 255) / 256, 256>>>(ei, et);
    k_scan<<<1, 32>>>();
    k_scatter<<<(N_EDGES + 255) / 256, 256>>>(ei, et);
    k_norm<<<2 * NUM_RELS, 256>>>(wf, wb);
    k_linear<<<(N_NODES + 255) / 256, 256>>>(x, lw, lb, out);
    k_edge<<<2 * NUM_RELS * CHUNKS, 256>>>(x, out);
}

// round 4
// speedup vs baseline: 1.3241x; 1.0245x over previous
#include <cuda_runtime.h>
#include <math.h>

#define IN_C   64
#define OUT_C  64
#define NUM_RELS 32
#define N_NODES 20000
#define N_EDGES 50000
#define CHUNKS 7

// ---------------- device scratch ----------------
__device__ __align__(16) int   g_cnt_src[N_NODES];
__device__ __align__(16) int   g_cnt_dst[N_NODES];
__device__ int   g_hist[NUM_RELS];
__device__ int   g_off[NUM_RELS + 1];
__device__ int   g_cursor[NUM_RELS];
__device__ int   g_ticket;
__device__ int   g_esrc[N_EDGES];
__device__ int   g_edst[N_EDGES];
__device__ __align__(16) float g_Wn[2 * NUM_RELS * IN_C * OUT_C];

// ---- packed f32x2 helpers ----
__device__ __forceinline__ void fma2(unsigned long long& d,
                                     unsigned long long a, unsigned long long b) {
    asm("fma.rn.f32x2 %0, %1, %2, %0;" : "+l"(d) : "l"(a), "l"(b));
}
__device__ __forceinline__ unsigned long long pack2(float v) {
    unsigned long long r;
    asm("mov.b64 %0, {%1, %1};" : "=l"(r) : "f"(v));
    return r;
}
__device__ __forceinline__ void mul2(unsigned long long& d,
                                     unsigned long long a, unsigned long long b) {
    asm("mul.rn.f32x2 %0, %1, %2;" : "=l"(d) : "l"(a), "l"(b));
}
__device__ __forceinline__ void unpack2(unsigned long long v, float& lo, float& hi) {
    asm("mov.b64 {%0, %1}, %2;" : "=f"(lo), "=f"(hi) : "l"(v));
}
__device__ __forceinline__ unsigned long long d_as_ull(double d) {
    return __double_as_longlong(d);
}

// ---------------- k0: zero counters (vectorized) ----------------
__global__ void k_zero() {
    int i = blockIdx.x * blockDim.x + threadIdx.x;
    int4 z = make_int4(0, 0, 0, 0);
    if (i < N_NODES / 4) ((int4*)g_cnt_src)[i] = z;
    else if (i < N_NODES / 2) ((int4*)g_cnt_dst)[i - N_NODES / 4] = z;
    if (i < NUM_RELS) { g_hist[i] = 0; g_cursor[i] = 0; }
    if (i == NUM_RELS) g_ticket = 0;
}

// ---------------- k1: degree counts + histogram + fused tail-block scan ------
__global__ void k_count(const int* __restrict__ ei, const int* __restrict__ et) {
    __shared__ int sh[NUM_RELS];
    __shared__ int isLast;
    if (threadIdx.x < NUM_RELS) sh[threadIdx.x] = 0;
    __syncthreads();
    int e = blockIdx.x * blockDim.x + threadIdx.x;
    if (e < N_EDGES) {
        atomicAdd(&g_cnt_src[ei[e]], 1);
        atomicAdd(&g_cnt_dst[ei[N_EDGES + e]], 1);
        atomicAdd(&sh[et[e]], 1);
    }
    __syncthreads();
    if (threadIdx.x < NUM_RELS && sh[threadIdx.x])
        atomicAdd(&g_hist[threadIdx.x], sh[threadIdx.x]);
    // last-block ticket -> 32-bin exclusive scan
    __threadfence();
    if (threadIdx.x == 0)
        isLast = (atomicAdd(&g_ticket, 1) == (int)gridDim.x - 1);
    __syncthreads();
    if (isLast && threadIdx.x < NUM_RELS) {
        __threadfence();
        int t = threadIdx.x;
        int s = g_hist[t];
        #pragma unroll
        for (int d = 1; d < 32; d <<= 1) {
            int n = __shfl_up_sync(0xffffffffu, s, d);
            if (t >= d) s += n;
        }
        g_off[t + 1] = s;
        if (t == 0) g_off[0] = 0;
    }
}

// ---------------- k3: block-aggregated counting-sort scatter ----------------
__global__ void k_scatter(const int* __restrict__ ei, const int* __restrict__ et) {
    __shared__ int lh[NUM_RELS];
    __shared__ int lbase[NUM_RELS];
    if (threadIdx.x < NUM_RELS) lh[threadIdx.x] = 0;
    __syncthreads();
    int e = blockIdx.x * blockDim.x + threadIdx.x;
    int t = -1, myrank = 0;
    if (e < N_EDGES) {
        t = et[e];
        myrank = atomicAdd(&lh[t], 1);
    }
    __syncthreads();
    if (threadIdx.x < NUM_RELS) {
        int c = lh[threadIdx.x];
        lbase[threadIdx.x] = c ? atomicAdd(&g_cursor[threadIdx.x], c) : 0;
    }
    __syncthreads();
    if (e < N_EDGES) {
        int p = g_off[t] + lbase[t] + myrank;
        g_esrc[p] = ei[e];
        g_edst[p] = ei[N_EDGES + e];
    }
}

// ---------------- k4: per-relation weight normalization ----------------
__global__ void k_norm(const float* __restrict__ wf, const float* __restrict__ wb) {
    int m = blockIdx.x;
    const float4* src = (const float4*)((m < NUM_RELS)
                        ? (wf + (size_t)m * 4096)
                        : (wb + (size_t)(m - NUM_RELS) * 4096));
    float4* dst = (float4*)(g_Wn + (size_t)m * 4096);
    __shared__ float red[8];
    float s = 0.f;
    float4 v[4];
    #pragma unroll
    for (int j = 0; j < 4; j++) {
        v[j] = src[threadIdx.x + j * 256];
        s += v[j].x * v[j].x + v[j].y * v[j].y + v[j].z * v[j].z + v[j].w * v[j].w;
    }
    #pragma unroll
    for (int d = 16; d > 0; d >>= 1) s += __shfl_xor_sync(0xffffffffu, s, d);
    if ((threadIdx.x & 31) == 0) red[threadIdx.x >> 5] = s;
    __syncthreads();
    if (threadIdx.x == 0) {
        float tot = 0.f;
        #pragma unroll
        for (int w = 0; w < 8; w++) tot += red[w];
        red[0] = 1.0f / (sqrtf(tot) + 0.01f);
    }
    __syncthreads();
    float scale = red[0];
    #pragma unroll
    for (int j = 0; j < 4; j++) {
        dst[threadIdx.x + j * 256] = make_float4(v[j].x * scale, v[j].y * scale,
                                                 v[j].z * scale, v[j].w * scale);
    }
}

// ---------------- k5: out = x @ lin_w^T + lin_b (f32x2) ----------------
__global__ void __launch_bounds__(256) k_linear(const float* __restrict__ x,
                                                const float* __restrict__ lw,
                                                const float* __restrict__ lb,
                                                float* __restrict__ out) {
    __shared__ __align__(16) float Ls[64 * 64];   // Ls[i*64+o] = lw[o*64+i]
    __shared__ float Bs[64];
    for (int j = threadIdx.x; j < 4096; j += 256) {
        int o = j >> 6, i = j & 63;
        Ls[i * 64 + o] = lw[j];
    }
    if (threadIdx.x < 64) Bs[threadIdx.x] = lb[threadIdx.x];
    __syncthreads();

    int n = blockIdx.x * 256 + threadIdx.x;
    if (n >= N_NODES) return;

    unsigned long long acc[32];
    #pragma unroll
    for (int k = 0; k < 32; k++) acc[k] = 0ull;

    const float4* xr = (const float4*)(x + (size_t)n * 64);
    #pragma unroll 1
    for (int i4 = 0; i4 < 16; i4++) {
        float4 v = xr[i4];
        float vs[4] = {v.x, v.y, v.z, v.w};
        #pragma unroll
        for (int j = 0; j < 4; j++) {
            unsigned long long vv = pack2(vs[j]);
            const double2* wrow = (const double2*)(Ls + ((i4 * 4 + j) << 6));
            #pragma unroll
            for (int o4 = 0; o4 < 16; o4++) {
                double2 w = wrow[o4];
                fma2(acc[2 * o4], vv, d_as_ull(w.x));
                fma2(acc[2 * o4 + 1], vv, d_as_ull(w.y));
            }
        }
    }
    float4* outr = (float4*)(out + (size_t)n * 64);
    const float4* B4 = (const float4*)Bs;
    #pragma unroll
    for (int o = 0; o < 16; o++) {
        float a0, a1, a2, a3;
        unpack2(acc[2 * o], a0, a1);
        unpack2(acc[2 * o + 1], a2, a3);
        float4 b = B4[o];
        outr[o] = make_float4(a0 + b.x, a1 + b.y, a2 + b.z, a3 + b.w);
    }
}

// ---------------- k6: edge message kernel (f32x2) ----------------
__global__ void __launch_bounds__(256) k_edge(const float* __restrict__ x,
                                              float* __restrict__ out) {
    __shared__ __align__(16) float Ws[4096];
    int b = blockIdx.x;
    int dir = b & 1;
    int t = (b >> 1) & 31;
    int chunk = b >> 6;          // 0..CHUNKS-1

    const float4* Wg = (const float4*)(g_Wn + (size_t)(dir * NUM_RELS + t) * 4096);
    float4* Ws4w = (float4*)Ws;
    for (int j = threadIdx.x; j < 1024; j += 256) Ws4w[j] = Wg[j];
    __syncthreads();

    int start = g_off[t], end = g_off[t + 1];

    for (int idx = start + chunk * 256 + threadIdx.x; idx < end; idx += 256 * CHUNKS) {
        int row, onode;
        float scale;
        if (dir == 0) {
            row = g_esrc[idx]; onode = g_edst[idx];
            scale = __fdividef(1.0f, (float)(g_cnt_src[row] + 1));
        } else {
            row = g_edst[idx]; onode = g_esrc[idx];
            scale = __fdividef(1.0f, (float)(g_cnt_dst[row] + 1));
        }

        unsigned long long acc[32];
        #pragma unroll
        for (int k = 0; k < 32; k++) acc[k] = 0ull;

        const float4* xr = (const float4*)(x + (size_t)row * 64);
        #pragma unroll 1
        for (int i4 = 0; i4 < 16; i4++) {
            float4 v = xr[i4];
            float vs[4] = {v.x, v.y, v.z, v.w};
            #pragma unroll
            for (int j = 0; j < 4; j++) {
                unsigned long long vv = pack2(vs[j]);
                const double2* wrow = (const double2*)(Ws + ((i4 * 4 + j) << 6));
                #pragma unroll
                for (int o4 = 0; o4 < 16; o4++) {
                    double2 w = wrow[o4];      // LDS.128 broadcast -> two f32x2
                    fma2(acc[2 * o4], vv, d_as_ull(w.x));
                    fma2(acc[2 * o4 + 1], vv, d_as_ull(w.y));
                }
            }
        }

        unsigned long long ss = pack2(scale);
        float* op = out + (size_t)onode * 64;
        #pragma unroll
        for (int o = 0; o < 16; o++) {
            unsigned long long p0, p1;
            mul2(p0, acc[2 * o], ss);
            mul2(p1, acc[2 * o + 1], ss);
            float a0, a1, a2, a3;
            unpack2(p0, a0, a1);
            unpack2(p1, a2, a3);
            asm volatile("red.global.add.v4.f32 [%0], {%1, %2, %3, %4};"
                         :: "l"(op + o * 4), "f"(a0), "f"(a1), "f"(a2), "f"(a3)
                         : "memory");
        }
    }
}

// ---------------- launch: fork-join overlap inside graph capture ------------
extern "C" void kernel_launch(void* const* d_in, const int* in_sizes, int n_in,
                              void* d_out, int out_size) {
    const float* x   = (const float*)d_in[0];
    const int*   ei  = (const int*)d_in[1];     // [2, E] int32
    const int*   et  = (const int*)d_in[2];     // [E]    int32
    const float* wf  = (const float*)d_in[3];
    const float* wb  = (const float*)d_in[4];
    const float* lw  = (const float*)d_in[5];
    const float* lb  = (const float*)d_in[6];
    float*       out = (float*)d_out;

    (void)in_sizes; (void)n_in; (void)out_size;

    cudaStream_t sB;
    cudaEvent_t evRoot, evB;
    cudaStreamCreateWithFlags(&sB, cudaStreamNonBlocking);
    cudaEventCreateWithFlags(&evRoot, cudaEventDisableTiming);
    cudaEventCreateWithFlags(&evB, cudaEventDisableTiming);

    // fork side stream off the (captured) legacy stream
    cudaEventRecord(evRoot, 0);
    cudaStreamWaitEvent(sB, evRoot, 0);

    // chain A (legacy stream): zero -> count(+scan) -> scatter
    k_zero<<<(N_NODES / 2 + 255) / 256, 256>>>();
    k_count<<<(N_EDGES + 255) / 256, 256>>>(ei, et);
    k_scatter<<<(N_EDGES + 255) / 256, 256>>>(ei, et);

    // chain B (side stream): weight norm -> dense linear (writes out)
    k_norm<<<2 * NUM_RELS, 256, 0, sB>>>(wf, wb);
    k_linear<<<(N_NODES + 255) / 256, 256, 0, sB>>>(x, lw, lb, out);
    cudaEventRecord(evB, sB);

    // join, then the big edge kernel
    cudaStreamWaitEvent(0, evB, 0);
    k_edge<<<2 * NUM_RELS * CHUNKS, 256>>>(x, out);

    cudaEventDestroy(evRoot);
    cudaEventDestroy(evB);
    cudaStreamDestroy(sB);
}